// round 2
// baseline (speedup 1.0000x reference)
#include <cuda_runtime.h>
#include <math.h>

// Problem constants
#define T_TOK   1024
#define HIDDEN  4096
#define QKV_N   6144          // H*HD + 2*KVH*HD = 4096 + 2048
#define NKV     3072
#define HD      128
#define NH      32
#define NKVH    8

// ---------------- scratch (device globals; no allocations allowed) ----------
__device__ float g_xqkv[T_TOK * QKV_N];       // 25.2 MB
__device__ float g_keys[NKV * NKVH * HD];     // 12.6 MB
__device__ float g_vals[NKV * NKVH * HD];     // 12.6 MB
__device__ float g_attn[T_TOK * HIDDEN];      // 16.8 MB

// ---------------- SGEMM: C[M,N] = A[M,K] * B[K,N], all row-major ------------
#define BM 128
#define BN 128
#define BK 16

__global__ __launch_bounds__(256) void sgemm_kernel(
    const float* __restrict__ A, const float* __restrict__ B,
    float* __restrict__ C, int M, int N, int K)
{
    __shared__ __align__(16) float As[BK][BM];
    __shared__ __align__(16) float Bs[BK][BN];

    const int tid = threadIdx.x;
    const int tx = tid & 15;          // 0..15 -> col block of 8
    const int ty = tid >> 4;          // 0..15 -> row block of 8
    const int row0 = blockIdx.y * BM;
    const int col0 = blockIdx.x * BN;

    // A load mapping: 128 rows x 16 k, float4 over k
    const int am = tid >> 2;          // 0..63 (two passes: +64)
    const int ak = (tid & 3) * 4;     // 0,4,8,12
    // B load mapping: 16 k x 128 cols, float4 over cols
    const int bk = tid >> 5;          // 0..7 (two passes: +8)
    const int bc = (tid & 31) * 4;

    float acc[8][8];
#pragma unroll
    for (int i = 0; i < 8; ++i)
#pragma unroll
        for (int j = 0; j < 8; ++j) acc[i][j] = 0.f;

    for (int k0 = 0; k0 < K; k0 += BK) {
#pragma unroll
        for (int p = 0; p < 2; ++p) {
            int m = am + p * 64;
            float4 v = *(const float4*)(A + (size_t)(row0 + m) * K + k0 + ak);
            As[ak + 0][m] = v.x; As[ak + 1][m] = v.y;
            As[ak + 2][m] = v.z; As[ak + 3][m] = v.w;
        }
#pragma unroll
        for (int p = 0; p < 2; ++p) {
            int kk = bk + p * 8;
            *(float4*)&Bs[kk][bc] = *(const float4*)(B + (size_t)(k0 + kk) * N + col0 + bc);
        }
        __syncthreads();

#pragma unroll
        for (int kk = 0; kk < BK; ++kk) {
            float4 a0 = *(const float4*)&As[kk][ty * 8];
            float4 a1 = *(const float4*)&As[kk][ty * 8 + 4];
            float4 b0 = *(const float4*)&Bs[kk][tx * 8];
            float4 b1 = *(const float4*)&Bs[kk][tx * 8 + 4];
            float ar[8] = {a0.x, a0.y, a0.z, a0.w, a1.x, a1.y, a1.z, a1.w};
            float br[8] = {b0.x, b0.y, b0.z, b0.w, b1.x, b1.y, b1.z, b1.w};
#pragma unroll
            for (int i = 0; i < 8; ++i)
#pragma unroll
                for (int j = 0; j < 8; ++j) acc[i][j] += ar[i] * br[j];
        }
        __syncthreads();
    }

#pragma unroll
    for (int i = 0; i < 8; ++i) {
        float* crow = C + (size_t)(row0 + ty * 8 + i) * N + col0 + tx * 8;
        float4 v0 = make_float4(acc[i][0], acc[i][1], acc[i][2], acc[i][3]);
        float4 v1 = make_float4(acc[i][4], acc[i][5], acc[i][6], acc[i][7]);
        *(float4*)crow       = v0;
        *(float4*)(crow + 4) = v1;
    }
}

// ---------------- RoPE (in place on q + k heads of g_xqkv) ------------------
// pairs: T_TOK tokens x 40 heads (32 q + 8 k) x 64 pairs
__global__ void rope_kernel(const int* __restrict__ seqstarts,
                            const int* __restrict__ start_pos)
{
    int idx = blockIdx.x * blockDim.x + threadIdx.x;
    if (idx >= T_TOK * 40 * 64) return;
    int t  = idx / (40 * 64);
    int r  = idx % (40 * 64);
    int hh = r / 64;
    int i  = r % 64;

    int b = 0;
#pragma unroll
    for (int j = 1; j < 4; ++j) if (t >= seqstarts[j]) b = j;
    int pos = t - seqstarts[b] + start_pos[b];

    // inv_freq = theta^(-i/64); ln(10000) = 9.210340371976184
    float inv = expf(-(float)i * (9.210340371976184f / 64.f));
    float ang = (float)pos * inv;
    float c = cosf(ang), s = sinf(ang);

    float* base = g_xqkv + (size_t)t * QKV_N + (size_t)hh * HD;
    float x1 = base[2 * i], x2 = base[2 * i + 1];
    base[2 * i]     = x1 * c - x2 * s;
    base[2 * i + 1] = x1 * s + x2 * c;
}

// ---------------- Gather merged keys/vals [NKV, KVH, HD] --------------------
__global__ void gather_kv_kernel(const float* __restrict__ kv_cache,
                                 const int* __restrict__ seqstarts,
                                 const int* __restrict__ kvstarts,
                                 const int* __restrict__ cachestarts,
                                 const int* __restrict__ start_pos)
{
    int idx = blockIdx.x * blockDim.x + threadIdx.x;
    if (idx >= NKV * NKVH * HD) return;
    int kvtok = idx / (NKVH * HD);
    int hd    = idx % (NKVH * HD);

    int b = 0;
#pragma unroll
    for (int j = 1; j < 4; ++j) if (kvtok >= kvstarts[j]) b = j;
    int pkv = kvtok - kvstarts[b];
    float k, v;
    if (pkv >= start_pos[b]) {
        int ni = seqstarts[b] + pkv - start_pos[b];
        ni = min(max(ni, 0), T_TOK - 1);
        k = g_xqkv[(size_t)ni * QKV_N + NH * HD + hd];            // roped xk
        v = g_xqkv[(size_t)ni * QKV_N + (NH + NKVH) * HD + hd];   // xv
    } else {
        int ci = cachestarts[b] + pkv;
        k = kv_cache[(size_t)ci * (NKVH * HD) + hd];                          // [0,0]
        v = kv_cache[(size_t)(8192 + ci) * (NKVH * HD) + hd];                 // [0,1]
    }
    g_keys[idx] = k;
    g_vals[idx] = v;
}

// ---------------- Attention: block = 16 queries x 2 heads (same kv head) ----
// rows R=32, kv tile KT=32, online softmax, K/V share one smem buffer.
#define ATT_R  32
#define ATT_KT 32

__global__ __launch_bounds__(256) void attn_kernel(
    const int* __restrict__ seqstarts,
    const int* __restrict__ kvstarts,
    const int* __restrict__ start_pos)
{
    __shared__ __align__(16) float Qs[HD][ATT_R];       // [d][row] 16 KB
    __shared__ __align__(16) float KVs[ATT_KT][132];    // padded, 16.9 KB
    __shared__ __align__(16) float Ss[ATT_KT][ATT_R];   // 4 KB
    __shared__ float rowm[ATT_R], rowl[ATT_R], rowf[ATT_R];
    __shared__ int s_kvlo[ATT_R], s_kvhi[ATT_R];
    __shared__ int s_min, s_max;

    const int tid   = threadIdx.x;
    const int qtile = blockIdx.x;   // 0..63
    const int hpair = blockIdx.y;   // 0..15
    const int kvh   = hpair >> 1;

    if (tid == 0) { s_min = 0x7fffffff; s_max = 0; }
    __syncthreads();
    if (tid < ATT_R) {
        int row = tid;
        int t = qtile * 16 + (row & 15);
        int b = 0;
#pragma unroll
        for (int j = 1; j < 4; ++j) if (t >= seqstarts[j]) b = j;
        int pos = t - seqstarts[b] + start_pos[b];
        int lo = kvstarts[b];
        s_kvlo[row] = lo;
        s_kvhi[row] = lo + pos;
        rowm[row] = -1e30f;
        rowl[row] = 0.f;
        atomicMin(&s_min, lo);
        atomicMax(&s_max, lo + pos);
    }
    // Q load: store transposed [d][row]
    {
        int row = tid >> 3;                         // 32 rows, 8 thr/row
        int t = qtile * 16 + (row & 15);
        int h = hpair * 2 + (row >> 4);
        const float* qptr = g_xqkv + (size_t)t * QKV_N + (size_t)h * HD;
#pragma unroll
        for (int k = 0; k < 4; ++k) {
            int d = ((tid & 7) + k * 8) * 4;
            float4 v = *(const float4*)(qptr + d);
            Qs[d + 0][row] = v.x; Qs[d + 1][row] = v.y;
            Qs[d + 2][row] = v.z; Qs[d + 3][row] = v.w;
        }
    }
    __syncthreads();

    const int kvmin = s_min;
    const int kvmax = s_max;
    const int rp = tid & 15;            // row pair
    const int r0 = rp * 2, r1 = r0 + 1;
    const int kp = tid >> 4;            // 0..15: kv-pair (scores) / col-group (PV)

    float acc0[8], acc1[8];
#pragma unroll
    for (int j = 0; j < 8; ++j) { acc0[j] = 0.f; acc1[j] = 0.f; }

    const float scale = 0.08838834764831843f;   // 1/sqrt(128)

    for (int kv0 = kvmin; kv0 <= kvmax; kv0 += ATT_KT) {
        // ---- load K tile ----
#pragma unroll
        for (int p = 0; p < 4; ++p) {
            int e = tid + p * 256;                 // 0..1023
            int kv = e >> 5;
            int f4 = (e & 31) * 4;
            int src = min(kv0 + kv, NKV - 1);
            *(float4*)&KVs[kv][f4] =
                *(const float4*)(g_keys + (size_t)src * (NKVH * HD) + kvh * HD + f4);
        }
        __syncthreads();

        // ---- scores: 2 rows x 2 kv per thread ----
        {
            const int k0i = kp * 2, k1i = k0i + 1;
            float s00 = 0.f, s01 = 0.f, s10 = 0.f, s11 = 0.f;
#pragma unroll 8
            for (int d = 0; d < HD; ++d) {
                float q0 = Qs[d][r0], q1 = Qs[d][r1];
                float ka = KVs[k0i][d], kb = KVs[k1i][d];
                s00 += q0 * ka; s01 += q0 * kb;
                s10 += q1 * ka; s11 += q1 * kb;
            }
            int kga = kv0 + k0i, kgb = kv0 + k1i;
            Ss[k0i][r0] = (kga >= s_kvlo[r0] && kga <= s_kvhi[r0]) ? s00 * scale : -1e30f;
            Ss[k1i][r0] = (kgb >= s_kvlo[r0] && kgb <= s_kvhi[r0]) ? s01 * scale : -1e30f;
            Ss[k0i][r1] = (kga >= s_kvlo[r1] && kga <= s_kvhi[r1]) ? s10 * scale : -1e30f;
            Ss[k1i][r1] = (kgb >= s_kvlo[r1] && kgb <= s_kvhi[r1]) ? s11 * scale : -1e30f;
        }
        __syncthreads();

        // ---- load V tile (reuse buffer) + online softmax on rows ----
#pragma unroll
        for (int p = 0; p < 4; ++p) {
            int e = tid + p * 256;
            int kv = e >> 5;
            int f4 = (e & 31) * 4;
            int src = min(kv0 + kv, NKV - 1);
            *(float4*)&KVs[kv][f4] =
                *(const float4*)(g_vals + (size_t)src * (NKVH * HD) + kvh * HD + f4);
        }
        if (tid < ATT_R) {
            int row = tid;
            float m = rowm[row], mnew = m;
#pragma unroll
            for (int kv = 0; kv < ATT_KT; ++kv) mnew = fmaxf(mnew, Ss[kv][row]);
            float f = expf(m - mnew);
            float l = rowl[row] * f;
#pragma unroll
            for (int kv = 0; kv < ATT_KT; ++kv) {
                float pe = expf(Ss[kv][row] - mnew);
                Ss[kv][row] = pe;
                l += pe;
            }
            rowm[row] = mnew; rowl[row] = l; rowf[row] = f;
        }
        __syncthreads();

        // ---- rescale + P*V ----
        {
            float f0 = rowf[r0], f1 = rowf[r1];
#pragma unroll
            for (int j = 0; j < 8; ++j) { acc0[j] *= f0; acc1[j] *= f1; }
            const int cb = kp * 8;
#pragma unroll
            for (int kv = 0; kv < ATT_KT; ++kv) {
                float p0 = Ss[kv][r0], p1 = Ss[kv][r1];
#pragma unroll
                for (int j = 0; j < 8; ++j) {
                    float v = KVs[kv][cb + j];
                    acc0[j] += p0 * v;
                    acc1[j] += p1 * v;
                }
            }
        }
        __syncthreads();
    }

    // ---- epilogue ----
    {
        const int cb = kp * 8;
        float li0 = 1.f / rowl[r0];
        float li1 = 1.f / rowl[r1];
        int t0 = qtile * 16 + (r0 & 15), h0 = hpair * 2 + (r0 >> 4);
        int t1 = qtile * 16 + (r1 & 15), h1 = hpair * 2 + (r1 >> 4);
        float* o0 = g_attn + (size_t)t0 * HIDDEN + h0 * HD + cb;
        float* o1 = g_attn + (size_t)t1 * HIDDEN + h1 * HD + cb;
#pragma unroll
        for (int j = 0; j < 8; ++j) {
            o0[j] = acc0[j] * li0;
            o1[j] = acc1[j] * li1;
        }
    }
}

// ---------------- launch ----------------------------------------------------
extern "C" void kernel_launch(void* const* d_in, const int* in_sizes, int n_in,
                              void* d_out, int out_size)
{
    const float* x          = (const float*)d_in[0];
    const float* wqkv       = (const float*)d_in[1];
    const float* wo         = (const float*)d_in[2];
    const float* kv_cache   = (const float*)d_in[3];
    const int*   seqstarts  = (const int*)d_in[4];
    const int*   kvstarts   = (const int*)d_in[5];
    const int*   cachestarts= (const int*)d_in[6];
    const int*   start_pos  = (const int*)d_in[7];
    float*       out        = (float*)d_out;

    float *p_xqkv = nullptr, *p_attn = nullptr;
    cudaGetSymbolAddress((void**)&p_xqkv, g_xqkv);
    cudaGetSymbolAddress((void**)&p_attn, g_attn);

    // 1) xqkv = x @ wqkv   [1024 x 6144]
    {
        dim3 grid(QKV_N / BN, T_TOK / BM);
        sgemm_kernel<<<grid, 256>>>(x, wqkv, p_xqkv, T_TOK, QKV_N, HIDDEN);
    }
    // 2) RoPE on q + k heads
    {
        int total = T_TOK * 40 * 64;
        rope_kernel<<<(total + 255) / 256, 256>>>(seqstarts, start_pos);
    }
    // 3) gather merged K/V
    {
        int total = NKV * NKVH * HD;
        gather_kv_kernel<<<(total + 255) / 256, 256>>>(kv_cache, seqstarts,
                                                       kvstarts, cachestarts,
                                                       start_pos);
    }
    // 4) attention
    {
        dim3 grid(T_TOK / 16, NH / 2);
        attn_kernel<<<grid, 256>>>(seqstarts, kvstarts, start_pos);
    }
    // 5) out = attn @ wo   [1024 x 4096]
    {
        dim3 grid(HIDDEN / BN, T_TOK / BM);
        sgemm_kernel<<<grid, 256>>>(p_attn, wo, out, T_TOK, HIDDEN, HIDDEN);
    }
}

// round 4
// speedup vs baseline: 2.5817x; 2.5817x over previous
#include <cuda_runtime.h>
#include <math.h>
#include <stdint.h>

// Problem constants
#define T_TOK   1024
#define HIDDEN  4096
#define QKV_N   6144          // H*HD + 2*KVH*HD
#define NKV     3072
#define HD      128
#define NH      32
#define NKVH    8

// ---------------- scratch (device globals; no allocations allowed) ----------
__device__ float g_xqkv[T_TOK * QKV_N];        // 25.2 MB
__device__ float g_keys[NKV * NKVH * HD];      // 12.6 MB
__device__ float g_vals[NKV * NKVH * HD];      // 12.6 MB
__device__ float g_attn[T_TOK * HIDDEN];       // 16.8 MB (tf32-rounded)
__device__ float g_xtf[T_TOK * HIDDEN];        // 16.8 MB (tf32-rounded x)
__device__ float g_wqkvT[QKV_N * HIDDEN];      // 100.7 MB (wqkv^T, tf32-rounded)
__device__ float g_woT[HIDDEN * HIDDEN];       // 67 MB    (wo^T, tf32-rounded)

// =====================  PTX helpers  =========================================
__device__ __forceinline__ uint32_t smem_u32(const void* p) {
    uint32_t a;
    asm("{ .reg .u64 t; cvta.to.shared.u64 t, %1; cvt.u32.u64 %0, t; }"
        : "=r"(a) : "l"(p));
    return a;
}
__device__ __forceinline__ uint32_t f2tf32(float x) {
    uint32_t u;
    asm("cvt.rna.tf32.f32 %0, %1;" : "=r"(u) : "f"(x));
    return u;
}
__device__ __forceinline__ void cp_async16(uint32_t smem, const void* gmem) {
    asm volatile("cp.async.cg.shared.global [%0], [%1], 16;"
                 :: "r"(smem), "l"(gmem) : "memory");
}
__device__ __forceinline__ void cp_commit() {
    asm volatile("cp.async.commit_group;" ::: "memory");
}
template <int N>
__device__ __forceinline__ void cp_wait() {
    asm volatile("cp.async.wait_group %0;" :: "n"(N) : "memory");
}
__device__ __forceinline__ void mma_tf32(float& c0, float& c1, float& c2, float& c3,
                                         uint32_t a0, uint32_t a1, uint32_t a2, uint32_t a3,
                                         uint32_t b0, uint32_t b1) {
    asm volatile(
        "mma.sync.aligned.m16n8k8.row.col.f32.tf32.tf32.f32 "
        "{%0,%1,%2,%3}, {%4,%5,%6,%7}, {%8,%9}, {%0,%1,%2,%3};"
        : "+f"(c0), "+f"(c1), "+f"(c2), "+f"(c3)
        : "r"(a0), "r"(a1), "r"(a2), "r"(a3), "r"(b0), "r"(b1));
}

// ===================== mma.sync tf32 GEMM ====================================
// C[M,N] = A[M,K] (row-major, tf32-rounded) @ BT[N,K]^T (row-major = K-major B)
// CTA 128x128x32, 256 threads, 8 warps of 64x32, 3-stage cp.async pipeline.
// Smem layout per matrix tile: [kblk(8)][row(128)][k%4(4)] floats.
#define GM_BM 128
#define GM_BN 128
#define GM_BK 32
#define GM_STAGES 3
#define GM_STAGE_FLOATS (2 * GM_BM * GM_BK)          // A + B per stage = 8192
#define GM_DYN_SMEM (GM_STAGES * GM_STAGE_FLOATS * 4)  // 96 KB

__global__ __launch_bounds__(256, 2)
void mma_gemm_tf32(const float* __restrict__ A, const float* __restrict__ BT,
                   float* __restrict__ C, int M, int N, int K)
{
    extern __shared__ uint32_t sm[];

    const int tid  = threadIdx.x;
    const int wid  = tid >> 5;
    const int lane = tid & 31;
    const int g    = lane >> 2;       // 0..7
    const int t4   = lane & 3;        // 0..3

    const int row0 = blockIdx.y * GM_BM;
    const int col0 = blockIdx.x * GM_BN;
    const int warp_m = (wid & 1) * 64;
    const int warp_n = (wid >> 1) * 32;

    // loader mapping: each thread: row = tid>>1 (0..127), 4 float4 k-blocks
    const int lrow = tid >> 1;
    const int lj0  = (tid & 1) * 4;   // k4-block start (0 or 4)

    const float* gA = A  + (size_t)(row0 + lrow) * K + lj0 * 4;
    const float* gB = BT + (size_t)(col0 + lrow) * K + lj0 * 4;

    const uint32_t smem_base = smem_u32(sm);
    // smem float offsets
    //  stage s: A at s*8192, B at s*8192 + 4096
    //  element (kblk, row, c): kblk*512 + row*4 + c

    float c[4][4][4];
#pragma unroll
    for (int i = 0; i < 4; ++i)
#pragma unroll
        for (int j = 0; j < 4; ++j)
#pragma unroll
            for (int q = 0; q < 4; ++q) c[i][j][q] = 0.f;

    const int NKB = K / GM_BK;

    auto load_stage = [&](int s, int kb) {
        const uint32_t sa = smem_base + (uint32_t)s * (GM_STAGE_FLOATS * 4);
        const float* pa = gA + (size_t)kb * GM_BK;
        const float* pb = gB + (size_t)kb * GM_BK;
#pragma unroll
        for (int j = 0; j < 4; ++j) {
            uint32_t off = (uint32_t)((lj0 + j) * 512 + lrow * 4) * 4;
            cp_async16(sa + off,          pa + j * 4);
            cp_async16(sa + 16384 + off,  pb + j * 4);
        }
    };

    // prologue
#pragma unroll
    for (int s = 0; s < GM_STAGES - 1; ++s) { load_stage(s, s); cp_commit(); }

    for (int kb = 0; kb < NKB; ++kb) {
        cp_wait<GM_STAGES - 2>();
        __syncthreads();

        if (kb + GM_STAGES - 1 < NKB)
            load_stage((kb + GM_STAGES - 1) % GM_STAGES, kb + GM_STAGES - 1);
        cp_commit();

        const uint32_t* sA = sm + (kb % GM_STAGES) * GM_STAGE_FLOATS;
        const uint32_t* sB = sA + GM_BM * GM_BK;

#pragma unroll
        for (int ks = 0; ks < 4; ++ks) {           // 4 k8-steps per BK=32
            const int kbase = ks * 1024;           // kb0*512 with kb0 = 2*ks
            uint32_t a[4][4];
#pragma unroll
            for (int i = 0; i < 4; ++i) {
                const uint32_t* pa = sA + kbase + (warp_m + i * 16 + g) * 4 + t4;
                a[i][0] = pa[0];
                a[i][1] = pa[32];      // +8 rows
                a[i][2] = pa[512];     // next k4 block
                a[i][3] = pa[544];
            }
#pragma unroll
            for (int j = 0; j < 4; ++j) {
                const uint32_t* pb = sB + kbase + (warp_n + j * 8 + g) * 4 + t4;
                uint32_t b0 = pb[0];
                uint32_t b1 = pb[512];
#pragma unroll
                for (int i = 0; i < 4; ++i)
                    mma_tf32(c[i][j][0], c[i][j][1], c[i][j][2], c[i][j][3],
                             a[i][0], a[i][1], a[i][2], a[i][3], b0, b1);
            }
        }
        __syncthreads();
    }

    // epilogue
#pragma unroll
    for (int i = 0; i < 4; ++i) {
        const int r0 = row0 + warp_m + i * 16 + g;
#pragma unroll
        for (int j = 0; j < 4; ++j) {
            const int cc = col0 + warp_n + j * 8 + t4 * 2;
            *(float2*)(C + (size_t)r0 * N + cc)       = make_float2(c[i][j][0], c[i][j][1]);
            *(float2*)(C + (size_t)(r0 + 8) * N + cc) = make_float2(c[i][j][2], c[i][j][3]);
        }
    }
}

// ---------------- transpose + tf32 round: out[c][r] = tf32(in[r][c]) --------
__global__ __launch_bounds__(256) void transpose_tf32(const float* __restrict__ in,
                                                      float* __restrict__ out,
                                                      int R, int C)
{
    __shared__ float t[32][33];
    const int bx = blockIdx.x * 32, by = blockIdx.y * 32;
    const int x = threadIdx.x & 31, y = threadIdx.x >> 5;
#pragma unroll
    for (int j = 0; j < 32; j += 8)
        t[y + j][x] = in[(size_t)(by + y + j) * C + bx + x];
    __syncthreads();
#pragma unroll
    for (int j = 0; j < 32; j += 8)
        out[(size_t)(bx + y + j) * R + by + x] =
            __uint_as_float(f2tf32(t[x][y + j]));
}

// ---------------- convert x to tf32-rounded copy ----------------------------
__global__ void convert_tf32_kernel(const float* __restrict__ in,
                                    float* __restrict__ out, int n)
{
    int i = (blockIdx.x * blockDim.x + threadIdx.x) * 4;
    if (i >= n) return;
    float4 v = *(const float4*)(in + i);
    v.x = __uint_as_float(f2tf32(v.x));
    v.y = __uint_as_float(f2tf32(v.y));
    v.z = __uint_as_float(f2tf32(v.z));
    v.w = __uint_as_float(f2tf32(v.w));
    *(float4*)(out + i) = v;
}

// ---------------- RoPE (in place on q + k heads of g_xqkv) ------------------
__global__ void rope_kernel(const int* __restrict__ seqstarts,
                            const int* __restrict__ start_pos)
{
    int idx = blockIdx.x * blockDim.x + threadIdx.x;
    if (idx >= T_TOK * 40 * 64) return;
    int t  = idx / (40 * 64);
    int r  = idx % (40 * 64);
    int hh = r / 64;
    int i  = r % 64;

    int b = 0;
#pragma unroll
    for (int j = 1; j < 4; ++j) if (t >= seqstarts[j]) b = j;
    int pos = t - seqstarts[b] + start_pos[b];

    float inv = expf(-(float)i * (9.210340371976184f / 64.f));
    float ang = (float)pos * inv;
    float c = cosf(ang), s = sinf(ang);

    float* base = g_xqkv + (size_t)t * QKV_N + (size_t)hh * HD;
    float x1 = base[2 * i], x2 = base[2 * i + 1];
    base[2 * i]     = x1 * c - x2 * s;
    base[2 * i + 1] = x1 * s + x2 * c;
}

// ---------------- Gather merged keys/vals [NKV, KVH, HD] --------------------
__global__ void gather_kv_kernel(const float* __restrict__ kv_cache,
                                 const int* __restrict__ seqstarts,
                                 const int* __restrict__ kvstarts,
                                 const int* __restrict__ cachestarts,
                                 const int* __restrict__ start_pos)
{
    int idx = blockIdx.x * blockDim.x + threadIdx.x;
    if (idx >= NKV * NKVH * HD) return;
    int kvtok = idx / (NKVH * HD);
    int hd    = idx % (NKVH * HD);

    int b = 0;
#pragma unroll
    for (int j = 1; j < 4; ++j) if (kvtok >= kvstarts[j]) b = j;
    int pkv = kvtok - kvstarts[b];
    float k, v;
    if (pkv >= start_pos[b]) {
        int ni = seqstarts[b] + pkv - start_pos[b];
        ni = min(max(ni, 0), T_TOK - 1);
        k = g_xqkv[(size_t)ni * QKV_N + NH * HD + hd];
        v = g_xqkv[(size_t)ni * QKV_N + (NH + NKVH) * HD + hd];
    } else {
        int ci = cachestarts[b] + pkv;
        k = kv_cache[(size_t)ci * (NKVH * HD) + hd];
        v = kv_cache[(size_t)(8192 + ci) * (NKVH * HD) + hd];
    }
    g_keys[idx] = k;
    g_vals[idx] = v;
}

// ---------------- Attention: block = 16 queries x 2 heads (same kv head) ----
#define ATT_R  32
#define ATT_KT 32

__global__ __launch_bounds__(256) void attn_kernel(
    const int* __restrict__ seqstarts,
    const int* __restrict__ kvstarts,
    const int* __restrict__ start_pos)
{
    __shared__ __align__(16) float Qs[HD][ATT_R];
    __shared__ __align__(16) float KVs[ATT_KT][132];
    __shared__ __align__(16) float Ss[ATT_KT][ATT_R];
    __shared__ float rowm[ATT_R], rowl[ATT_R], rowf[ATT_R];
    __shared__ int s_kvlo[ATT_R], s_kvhi[ATT_R];
    __shared__ int s_min, s_max;

    const int tid   = threadIdx.x;
    const int qtile = blockIdx.x;
    const int hpair = blockIdx.y;
    const int kvh   = hpair >> 1;

    if (tid == 0) { s_min = 0x7fffffff; s_max = 0; }
    __syncthreads();
    if (tid < ATT_R) {
        int row = tid;
        int t = qtile * 16 + (row & 15);
        int b = 0;
#pragma unroll
        for (int j = 1; j < 4; ++j) if (t >= seqstarts[j]) b = j;
        int pos = t - seqstarts[b] + start_pos[b];
        int lo = kvstarts[b];
        s_kvlo[row] = lo;
        s_kvhi[row] = lo + pos;
        rowm[row] = -1e30f;
        rowl[row] = 0.f;
        atomicMin(&s_min, lo);
        atomicMax(&s_max, lo + pos);
    }
    {
        int row = tid >> 3;
        int t = qtile * 16 + (row & 15);
        int h = hpair * 2 + (row >> 4);
        const float* qptr = g_xqkv + (size_t)t * QKV_N + (size_t)h * HD;
#pragma unroll
        for (int k = 0; k < 4; ++k) {
            int d = ((tid & 7) + k * 8) * 4;
            float4 v = *(const float4*)(qptr + d);
            Qs[d + 0][row] = v.x; Qs[d + 1][row] = v.y;
            Qs[d + 2][row] = v.z; Qs[d + 3][row] = v.w;
        }
    }
    __syncthreads();

    const int kvmin = s_min;
    const int kvmax = s_max;
    const int rp = tid & 15;
    const int r0 = rp * 2, r1 = r0 + 1;
    const int kp = tid >> 4;

    float acc0[8], acc1[8];
#pragma unroll
    for (int j = 0; j < 8; ++j) { acc0[j] = 0.f; acc1[j] = 0.f; }

    const float scale = 0.08838834764831843f;

    for (int kv0 = kvmin; kv0 <= kvmax; kv0 += ATT_KT) {
#pragma unroll
        for (int p = 0; p < 4; ++p) {
            int e = tid + p * 256;
            int kv = e >> 5;
            int f4 = (e & 31) * 4;
            int src = min(kv0 + kv, NKV - 1);
            *(float4*)&KVs[kv][f4] =
                *(const float4*)(g_keys + (size_t)src * (NKVH * HD) + kvh * HD + f4);
        }
        __syncthreads();

        {
            const int k0i = kp * 2, k1i = k0i + 1;
            float s00 = 0.f, s01 = 0.f, s10 = 0.f, s11 = 0.f;
#pragma unroll 8
            for (int d = 0; d < HD; ++d) {
                float q0 = Qs[d][r0], q1 = Qs[d][r1];
                float ka = KVs[k0i][d], kb = KVs[k1i][d];
                s00 += q0 * ka; s01 += q0 * kb;
                s10 += q1 * ka; s11 += q1 * kb;
            }
            int kga = kv0 + k0i, kgb = kv0 + k1i;
            Ss[k0i][r0] = (kga >= s_kvlo[r0] && kga <= s_kvhi[r0]) ? s00 * scale : -1e30f;
            Ss[k1i][r0] = (kgb >= s_kvlo[r0] && kgb <= s_kvhi[r0]) ? s01 * scale : -1e30f;
            Ss[k0i][r1] = (kga >= s_kvlo[r1] && kga <= s_kvhi[r1]) ? s10 * scale : -1e30f;
            Ss[k1i][r1] = (kgb >= s_kvlo[r1] && kgb <= s_kvhi[r1]) ? s11 * scale : -1e30f;
        }
        __syncthreads();

#pragma unroll
        for (int p = 0; p < 4; ++p) {
            int e = tid + p * 256;
            int kv = e >> 5;
            int f4 = (e & 31) * 4;
            int src = min(kv0 + kv, NKV - 1);
            *(float4*)&KVs[kv][f4] =
                *(const float4*)(g_vals + (size_t)src * (NKVH * HD) + kvh * HD + f4);
        }
        if (tid < ATT_R) {
            int row = tid;
            float m = rowm[row], mnew = m;
#pragma unroll
            for (int kv = 0; kv < ATT_KT; ++kv) mnew = fmaxf(mnew, Ss[kv][row]);
            float f = expf(m - mnew);
            float l = rowl[row] * f;
#pragma unroll
            for (int kv = 0; kv < ATT_KT; ++kv) {
                float pe = expf(Ss[kv][row] - mnew);
                Ss[kv][row] = pe;
                l += pe;
            }
            rowm[row] = mnew; rowl[row] = l; rowf[row] = f;
        }
        __syncthreads();

        {
            float f0 = rowf[r0], f1 = rowf[r1];
#pragma unroll
            for (int j = 0; j < 8; ++j) { acc0[j] *= f0; acc1[j] *= f1; }
            const int cb = kp * 8;
#pragma unroll
            for (int kv = 0; kv < ATT_KT; ++kv) {
                float p0 = Ss[kv][r0], p1 = Ss[kv][r1];
#pragma unroll
                for (int j = 0; j < 8; ++j) {
                    float v = KVs[kv][cb + j];
                    acc0[j] += p0 * v;
                    acc1[j] += p1 * v;
                }
            }
        }
        __syncthreads();
    }

    // epilogue: write tf32-rounded (consumed only by the WO GEMM)
    {
        const int cb = kp * 8;
        float li0 = 1.f / rowl[r0];
        float li1 = 1.f / rowl[r1];
        int t0 = qtile * 16 + (r0 & 15), h0 = hpair * 2 + (r0 >> 4);
        int t1 = qtile * 16 + (r1 & 15), h1 = hpair * 2 + (r1 >> 4);
        float* o0 = g_attn + (size_t)t0 * HIDDEN + h0 * HD + cb;
        float* o1 = g_attn + (size_t)t1 * HIDDEN + h1 * HD + cb;
#pragma unroll
        for (int j = 0; j < 8; ++j) {
            o0[j] = __uint_as_float(f2tf32(acc0[j] * li0));
            o1[j] = __uint_as_float(f2tf32(acc1[j] * li1));
        }
    }
}

// ---------------- launch ----------------------------------------------------
extern "C" void kernel_launch(void* const* d_in, const int* in_sizes, int n_in,
                              void* d_out, int out_size)
{
    const float* x          = (const float*)d_in[0];
    const float* wqkv       = (const float*)d_in[1];
    const float* wo         = (const float*)d_in[2];
    const float* kv_cache   = (const float*)d_in[3];
    const int*   seqstarts  = (const int*)d_in[4];
    const int*   kvstarts   = (const int*)d_in[5];
    const int*   cachestarts= (const int*)d_in[6];
    const int*   start_pos  = (const int*)d_in[7];
    float*       out        = (float*)d_out;

    float *p_xqkv, *p_attn, *p_xtf, *p_wqkvT, *p_woT;
    cudaGetSymbolAddress((void**)&p_xqkv, g_xqkv);
    cudaGetSymbolAddress((void**)&p_attn, g_attn);
    cudaGetSymbolAddress((void**)&p_xtf, g_xtf);
    cudaGetSymbolAddress((void**)&p_wqkvT, g_wqkvT);
    cudaGetSymbolAddress((void**)&p_woT, g_woT);

    cudaFuncSetAttribute(mma_gemm_tf32, cudaFuncAttributeMaxDynamicSharedMemorySize,
                         GM_DYN_SMEM);

    // 0) prepare tf32 operands
    {
        dim3 grid(QKV_N / 32, HIDDEN / 32);
        transpose_tf32<<<grid, 256>>>(wqkv, p_wqkvT, HIDDEN, QKV_N);
        dim3 grid2(HIDDEN / 32, HIDDEN / 32);
        transpose_tf32<<<grid2, 256>>>(wo, p_woT, HIDDEN, HIDDEN);
        int n = T_TOK * HIDDEN;
        convert_tf32_kernel<<<(n / 4 + 255) / 256, 256>>>(x, p_xtf, n);
    }
    // 1) xqkv = x @ wqkv   (tf32 mma.sync)
    {
        dim3 grid(QKV_N / GM_BN, T_TOK / GM_BM);
        mma_gemm_tf32<<<grid, 256, GM_DYN_SMEM>>>(p_xtf, p_wqkvT, p_xqkv,
                                                  T_TOK, QKV_N, HIDDEN);
    }
    // 2) RoPE
    {
        int total = T_TOK * 40 * 64;
        rope_kernel<<<(total + 255) / 256, 256>>>(seqstarts, start_pos);
    }
    // 3) gather merged K/V
    {
        int total = NKV * NKVH * HD;
        gather_kv_kernel<<<(total + 255) / 256, 256>>>(kv_cache, seqstarts,
                                                       kvstarts, cachestarts,
                                                       start_pos);
    }
    // 4) attention
    {
        dim3 grid(T_TOK / 16, NH / 2);
        attn_kernel<<<grid, 256>>>(seqstarts, kvstarts, start_pos);
    }
    // 5) out = attn @ wo   (tf32 mma.sync)
    {
        dim3 grid(HIDDEN / GM_BN, T_TOK / GM_BM);
        mma_gemm_tf32<<<grid, 256, GM_DYN_SMEM>>>(p_attn, p_woT, out,
                                                  T_TOK, HIDDEN, HIDDEN);
    }
}